// round 9
// baseline (speedup 1.0000x reference)
#include <cuda_runtime.h>

#define B_  4
#define N_  2048
#define V_  12
#define C_  50
#define P_  16384   /* H*W = 128*128 */
#define RSL 6       /* log2 row stride: 64 floats = 256 B aligned rows */
#define GN_ 8       /* n-items per lift block (= warps per block) */

// Winner keys, encoded key+1 so 0 == "no winner". Statically zero-initialized;
// lift resets each entry to 0 after reading -> clean state every replay.
__device__ int g_winner[B_ * V_ * N_];

// Per-(bv,pixel) RAW logit rows (50 floats used, 64 stride), written only for
// mask-passing pixels (~7%). Cols 50..63 never written -> always zero.
__device__ float g_feat[((size_t)B_ * V_ * P_) << RSL];   // ~201 MB
// Index of a never-written row inside g_feat is not available, so keep a
// dedicated zero row; lift uses 32-bit indices into g_feat, so no-winner views
// are redirected with a branchless pointer select as before.
__device__ float g_zero[1 << RSL];

// K1 — one thread per pixel, single pass, x[50] in registers. NO early
// returns: p2p / parts_nb / pred loads all issue unconditionally so the warp
// never serializes p2p-latency -> pred-latency (R8: worth 18us).
__global__ __launch_bounds__(256) void argmax_scatter_kernel(
    const float* __restrict__ pred,        // (B,V,C,P)
    const int*   __restrict__ p2p,         // (B,V,P)
    const int*   __restrict__ parts_nb)    // (B,)
{
    int t = blockIdx.x * blockDim.x + threadIdx.x;
    int bv = t >> 14;                      // / P_
    int p  = t & (P_ - 1);
    int b  = bv / V_;

    int point = __ldcs(&p2p[t]);           // issued alongside pred loads
    int pn    = parts_nb[b];

    const float* base = pred + (size_t)bv * C_ * P_ + p;
    float x[C_];
    float mx = -3.402823466e+38f;
    int   am = 0;
#pragma unroll
    for (int c = 0; c < C_; c++) {
        x[c] = __ldcs(&base[(size_t)c * P_]);
        if (x[c] > mx) { mx = x[c]; am = c; }   // '>' keeps first occurrence (jnp.argmax)
    }

    if (point >= 0 && am >= 1 && am <= pn) {
        float* row = g_feat + ((size_t)t << RSL);   // 256B-aligned row
        float4* r4 = (float4*)row;
#pragma unroll
        for (int c4 = 0; c4 < C_ / 4; c4++)         // 48 floats as STG.128
            r4[c4] = make_float4(x[4*c4], x[4*c4+1], x[4*c4+2], x[4*c4+3]);
        ((float2*)row)[24] = make_float2(x[48], x[49]);

        int key = am * P_ + p + 1;             // +1: 0 means "no winner"
        atomicMax(&g_winner[bv * N_ + (point & (N_ - 1))], key);
    }
}

// K2 — fused lift: one WARP per (b,n), 8 warps/block.
//   phase 0: lanes 0..V-1 read+reset winner keys, read view weights;
//            per-warp reciprocal of the valid-view count (MUFU, not FDIV)
//   phase 1: 24 independent LDG->STS pairs stage the 12 rows into smem
//            (32-bit g_feat indices: max index 50.3M < 2^31)
//   phase 2: per-view softmax from smem + weighted accumulate; fold 1/denom
//            into the accumulators (2 FMUL/warp-lane)
//   phase 3: smem transpose, pure copy out (NO divides)
__global__ __launch_bounds__(256) void lift_kernel(
    const float* __restrict__ vw,          // (B,V)
    float*       __restrict__ out)         // (B,C,N)
{
    const unsigned FULL = 0xFFFFFFFFu;
    int blk  = blockIdx.x;
    int b    = blk / (N_ / GN_);
    int n0   = (blk - b * (N_ / GN_)) * GN_;
    int wid  = threadIdx.x >> 5;
    int lane = threadIdx.x & 31;
    int n    = n0 + wid;

    __shared__ float s_row[GN_][V_][64];   // 24.5 KB staged rows
    __shared__ float s_acc[C_][GN_ + 1];   // +1 pad: conflict-free transpose

    // phase 0
    int key = 0;
    float w = 0.f;
    if (lane < V_) {
        int* wp = &g_winner[(b * V_ + lane) * N_ + n];
        key = *wp;
        *wp = 0;                           // reset for next graph replay
        w = vw[b * V_ + lane];
    }
    unsigned ball = __ballot_sync(FULL, key > 0);
    float rdn = __fdividef(1.0f, fmaxf((float)__popc(ball), 1.f));

    // phase 1: stage all 12 rows (24 independent loads), same-lane smem slots
#pragma unroll
    for (int v = 0; v < V_; v++) {
        int kv = __shfl_sync(FULL, key, v);
        unsigned idx = ((unsigned)(b * V_ + v) * P_ + (((unsigned)(kv - 1)) & (P_ - 1))) << RSL;
        const float* row = (kv > 0) ? &g_feat[idx] : g_zero;
        s_row[wid][v][lane]      = __ldg(&row[lane]);
        s_row[wid][v][lane + 32] = __ldg(&row[lane + 32]);
    }

    // phase 2: softmax per view from smem + weighted accumulate
    float acc0 = 0.f, acc1 = 0.f;
#pragma unroll
    for (int v = 0; v < V_; v++) {
        int   kv = __shfl_sync(FULL, key, v);
        float wv = __shfl_sync(FULL, w,   v);
        float e0 = __expf(s_row[wid][v][lane]);
        float e1 = (lane + 32 < C_) ? __expf(s_row[wid][v][lane + 32]) : 0.f;
        float se = e0 + e1;
#pragma unroll
        for (int s = 16; s >= 1; s >>= 1)
            se += __shfl_xor_sync(FULL, se, s);
        float inv = (kv > 0) ? __fdividef(wv, se) : 0.f;
        acc0 += inv * e0;
        acc1 += inv * e1;
    }
    acc0 *= rdn;                           // fold denom here: phase 3 = copy
    acc1 *= rdn;

    s_acc[lane][wid] = acc0;
    if (lane + 32 < C_) s_acc[lane + 32][wid] = acc1;
    __syncthreads();

    // phase 3: 400 outputs per block, coalesced along n, no divides
#pragma unroll
    for (int i = threadIdx.x; i < C_ * GN_; i += 256) {
        int c = i >> 3, j = i & (GN_ - 1);
        out[((size_t)b * C_ + c) * N_ + n0 + j] = s_acc[c][j];
    }
}

extern "C" void kernel_launch(void* const* d_in, const int* in_sizes, int n_in,
                              void* d_out, int out_size) {
    // inputs: 0 points (unused), 1 predictions_2d, 2 rendered_pix_to_point,
    //         3 views_weights, 4 parts_nb
    const float* pred     = (const float*)d_in[1];
    const int*   p2p      = (const int*)  d_in[2];
    const float* vw       = (const float*)d_in[3];
    const int*   parts_nb = (const int*)  d_in[4];
    float*       out      = (float*)d_out;

    argmax_scatter_kernel<<<(B_ * V_ * P_) / 256, 256>>>(pred, p2p, parts_nb);
    lift_kernel<<<(B_ * N_) / GN_, 256>>>(vw, out);
}

// round 10
// speedup vs baseline: 1.4749x; 1.4749x over previous
#include <cuda_runtime.h>

#define B_  4
#define N_  2048
#define V_  12
#define C_  50
#define P_  16384   /* H*W = 128*128 */
#define RSL 6       /* log2 row stride: 64 floats = 256 B aligned rows */
#define GN_ 8       /* n-items per lift block (= warps per block) */

// Winner keys, encoded key+1 so 0 == "no winner". Statically zero-initialized;
// lift resets each entry to 0 after reading -> clean state every replay.
__device__ int g_winner[B_ * V_ * N_];

// Per-(bv,pixel) RAW logit rows (50 floats used, 64 stride), written only for
// mask-passing pixels (~7%). Cols 50..63 never written -> always zero.
__device__ float g_feat[((size_t)B_ * V_ * P_) << RSL];   // ~201 MB
// Never written -> always zero. Target for views without a winner.
__device__ float g_zero[1 << RSL];

// K1 — one thread per pixel, single pass, x[50] in registers. NO early
// returns: p2p / parts_nb / pred loads all issue unconditionally so the warp
// never serializes p2p-latency -> pred-latency (R8: worth 18us).
__global__ __launch_bounds__(256) void argmax_scatter_kernel(
    const float* __restrict__ pred,        // (B,V,C,P)
    const int*   __restrict__ p2p,         // (B,V,P)
    const int*   __restrict__ parts_nb)    // (B,)
{
    int t = blockIdx.x * blockDim.x + threadIdx.x;
    int bv = t >> 14;                      // / P_
    int p  = t & (P_ - 1);
    int b  = bv / V_;

    int point = __ldcs(&p2p[t]);           // issued alongside pred loads
    int pn    = parts_nb[b];

    const float* base = pred + (size_t)bv * C_ * P_ + p;
    float x[C_];
    float mx = -3.402823466e+38f;
    int   am = 0;
#pragma unroll
    for (int c = 0; c < C_; c++) {
        x[c] = __ldcs(&base[(size_t)c * P_]);
        if (x[c] > mx) { mx = x[c]; am = c; }   // '>' keeps first occurrence (jnp.argmax)
    }

    if (point >= 0 && am >= 1 && am <= pn) {
        float* row = g_feat + ((size_t)t << RSL);   // 256B-aligned row
        float4* r4 = (float4*)row;
#pragma unroll
        for (int c4 = 0; c4 < C_ / 4; c4++)         // 48 floats as STG.128
            r4[c4] = make_float4(x[4*c4], x[4*c4+1], x[4*c4+2], x[4*c4+3]);
        ((float2*)row)[24] = make_float2(x[48], x[49]);

        int key = am * P_ + p + 1;             // +1: 0 means "no winner"
        atomicMax(&g_winner[bv * N_ + (point & (N_ - 1))], key);
    }
}

// K2 — fused lift: EXACT R8 form (measured 12.9us) with ONE change:
// s_dn stores the per-warp RECIPROCAL of the valid-view count, and phase 3
// multiplies instead of issuing an IEEE divide per output.
__global__ __launch_bounds__(256) void lift_kernel(
    const float* __restrict__ vw,          // (B,V)
    float*       __restrict__ out)         // (B,C,N)
{
    const unsigned FULL = 0xFFFFFFFFu;
    int blk  = blockIdx.x;
    int b    = blk / (N_ / GN_);
    int n0   = (blk - b * (N_ / GN_)) * GN_;
    int wid  = threadIdx.x >> 5;
    int lane = threadIdx.x & 31;
    int n    = n0 + wid;

    __shared__ float s_row[GN_][V_][64];   // 24.5 KB staged rows
    __shared__ float s_acc[C_][GN_ + 1];   // +1 pad: conflict-free transpose
    __shared__ float s_dn[GN_];            // reciprocal of denom

    // phase 0
    int key = 0;
    float w = 0.f;
    if (lane < V_) {
        int* wp = &g_winner[(b * V_ + lane) * N_ + n];
        key = *wp;
        *wp = 0;                           // reset for next graph replay
        w = vw[b * V_ + lane];
    }
    unsigned ball = __ballot_sync(FULL, key > 0);
    float denom = fmaxf((float)__popc(ball), 1.f);

    // phase 1: stage all 12 rows (24 independent loads), same-lane smem slots
#pragma unroll
    for (int v = 0; v < V_; v++) {
        int kv = __shfl_sync(FULL, key, v);
        const float* row = (kv > 0)
            ? g_feat + (((size_t)(b * V_ + v) * P_ + ((kv - 1) & (P_ - 1))) << RSL)
            : g_zero;
        s_row[wid][v][lane]      = __ldg(&row[lane]);
        s_row[wid][v][lane + 32] = __ldg(&row[lane + 32]);
    }

    // phase 2: softmax per view from smem + weighted accumulate
    float acc0 = 0.f, acc1 = 0.f;
#pragma unroll
    for (int v = 0; v < V_; v++) {
        int   kv = __shfl_sync(FULL, key, v);
        float wv = __shfl_sync(FULL, w,   v);
        float e0 = __expf(s_row[wid][v][lane]);
        float e1 = (lane + 32 < C_) ? __expf(s_row[wid][v][lane + 32]) : 0.f;
        float se = e0 + e1;
#pragma unroll
        for (int s = 16; s >= 1; s >>= 1)
            se += __shfl_xor_sync(FULL, se, s);
        float inv = (kv > 0) ? __fdividef(wv, se) : 0.f;
        acc0 += inv * e0;
        acc1 += inv * e1;
    }

    s_acc[lane][wid] = acc0;
    if (lane + 32 < C_) s_acc[lane + 32][wid] = acc1;
    if (lane == 0) s_dn[wid] = __fdividef(1.0f, denom);   // reciprocal, once/warp
    __syncthreads();

    // phase 3: 400 outputs per block, coalesced along n, FMUL not FDIV
#pragma unroll
    for (int i = threadIdx.x; i < C_ * GN_; i += 256) {
        int c = i >> 3, j = i & (GN_ - 1);
        out[((size_t)b * C_ + c) * N_ + n0 + j] = s_acc[c][j] * s_dn[j];
    }
}

extern "C" void kernel_launch(void* const* d_in, const int* in_sizes, int n_in,
                              void* d_out, int out_size) {
    // inputs: 0 points (unused), 1 predictions_2d, 2 rendered_pix_to_point,
    //         3 views_weights, 4 parts_nb
    const float* pred     = (const float*)d_in[1];
    const int*   p2p      = (const int*)  d_in[2];
    const float* vw       = (const float*)d_in[3];
    const int*   parts_nb = (const int*)  d_in[4];
    float*       out      = (float*)d_out;

    argmax_scatter_kernel<<<(B_ * V_ * P_) / 256, 256>>>(pred, p2p, parts_nb);
    lift_kernel<<<(B_ * N_) / GN_, 256>>>(vw, out);
}